// round 1
// baseline (speedup 1.0000x reference)
#include <cuda_runtime.h>
#include <float.h>
#include <math.h>

// Problem constants (fixed by the dataset)
#define BSZ      64
#define NH       32
#define KVH      8
#define GROUPS   4          // NH / KVH
#define HD       128
#define BS       16         // paged block size
#define BPS      128        // blocks per sequence
#define MAX_CTX  2048

// Split-KV config
#define CHUNK    256
#define NCHUNK   (MAX_CTX / CHUNK)   // 8
#define NTHREADS 256
#define NWARPS   (NTHREADS / 32)     // 8

#define SCALE 0.08838834764831845f   // 1/sqrt(128)

// Scratch for split-KV partials (static device globals: allocation-free)
__device__ float g_pout[(size_t)BSZ * KVH * NCHUNK * GROUPS * HD]; // 8 MB
__device__ float g_pm[BSZ * KVH * NCHUNK * GROUPS];
__device__ float g_pl[BSZ * KVH * NCHUNK * GROUPS];

__global__ __launch_bounds__(NTHREADS)
void attn_chunk_kernel(const float* __restrict__ q,
                       const float* __restrict__ kc,
                       const float* __restrict__ vc,
                       const int*   __restrict__ bt,
                       const int*   __restrict__ lens)
{
    const int bid   = blockIdx.x;
    const int chunk = bid % NCHUNK;
    const int kvh   = (bid / NCHUNK) % KVH;
    const int seq   = bid / (NCHUNK * KVH);
    const int tid   = threadIdx.x;
    const int warp  = tid >> 5;
    const int lane  = tid & 31;

    const int len    = lens[seq];
    const int cstart = chunk * CHUNK;
    const int sk     = seq * KVH + kvh;
    const int pbase  = (sk * NCHUNK + chunk) * GROUPS;   // index into g_pm/g_pl (per g)

    if (cstart >= len) {
        if (tid < GROUPS) { g_pm[pbase + tid] = -FLT_MAX; g_pl[pbase + tid] = 0.0f; }
        return;
    }

    __shared__ float s_sc[GROUPS][CHUNK];          // scores -> probs (4 KB)
    __shared__ float s_red[NWARPS][GROUPS * HD];   // PV cross-warp reduce (16 KB)

    // ---------------- Phase 1: scores = (Q . K) * scale ----------------
    // Lane layout: g = lane & 3, dims [ (lane>>2)*16 , +16 ).
    // Four lanes share each 16-dim K slice (HW coalesces duplicate addresses),
    // and the 4-head reduction needs only 3 butterfly shuffles.
    {
        const int g  = lane & 3;
        const int d0 = (lane >> 2) * 16;
        const float* qp = q + ((size_t)(seq * NH + kvh * GROUPS + g)) * HD + d0;
        const float4 q0 = *(const float4*)(qp + 0);
        const float4 q1 = *(const float4*)(qp + 4);
        const float4 q2 = *(const float4*)(qp + 8);
        const float4 q3 = *(const float4*)(qp + 12);

        const int t0 = warp * (CHUNK / NWARPS);
        const int t1 = t0 + (CHUNK / NWARPS);
        #pragma unroll 2
        for (int t = t0; t < t1; ++t) {
            const int gt = cstart + t;
            float val;
            if (gt < len) {
                const int blk = bt[seq * BPS + (gt >> 4)];
                const float* kp = kc + (((size_t)blk * KVH + kvh) * BS + (gt & 15)) * HD + d0;
                const float4 k0 = *(const float4*)(kp + 0);
                const float4 k1 = *(const float4*)(kp + 4);
                const float4 k2 = *(const float4*)(kp + 8);
                const float4 k3 = *(const float4*)(kp + 12);
                float s = q0.x*k0.x + q0.y*k0.y + q0.z*k0.z + q0.w*k0.w
                        + q1.x*k1.x + q1.y*k1.y + q1.z*k1.z + q1.w*k1.w
                        + q2.x*k2.x + q2.y*k2.y + q2.z*k2.z + q2.w*k2.w
                        + q3.x*k3.x + q3.y*k3.y + q3.z*k3.z + q3.w*k3.w;
                // reduce across the 8 dim-slices (lanes sharing lane&3)
                s += __shfl_xor_sync(0xffffffffu, s, 4);
                s += __shfl_xor_sync(0xffffffffu, s, 8);
                s += __shfl_xor_sync(0xffffffffu, s, 16);
                val = s * SCALE;
            } else {
                val = -FLT_MAX;
            }
            if (lane < GROUPS) s_sc[lane][t] = val;   // lane 0..3 hold g=0..3 sums
        }
    }
    __syncthreads();

    // ---------------- Phase 2: chunk-local softmax (m, l, probs) -------
    if (warp < GROUPS) {
        const int g = warp;
        float m = -FLT_MAX;
        #pragma unroll
        for (int t = lane; t < CHUNK; t += 32) m = fmaxf(m, s_sc[g][t]);
        #pragma unroll
        for (int off = 16; off > 0; off >>= 1)
            m = fmaxf(m, __shfl_xor_sync(0xffffffffu, m, off));

        float l = 0.0f;
        #pragma unroll
        for (int t = lane; t < CHUNK; t += 32) {
            const float s = s_sc[g][t];
            const float p = (s > -0.5f * FLT_MAX) ? __expf(s - m) : 0.0f;
            s_sc[g][t] = p;
            l += p;
        }
        #pragma unroll
        for (int off = 16; off > 0; off >>= 1)
            l += __shfl_xor_sync(0xffffffffu, l, off);

        if (lane == 0) {
            g_pm[pbase + g] = m;
            g_pl[pbase + g] = l;
        }
    }
    __syncthreads();

    // ---------------- Phase 3: O_partial = P . V ------------------------
    // Thread layout: d4 = tid&31 (float4 column), slice = warp id (token stride 8).
    {
        const int d4 = tid & 31;
        float acc[GROUPS][4];
        #pragma unroll
        for (int g = 0; g < GROUPS; ++g) {
            acc[g][0] = 0.f; acc[g][1] = 0.f; acc[g][2] = 0.f; acc[g][3] = 0.f;
        }

        #pragma unroll 2
        for (int t = warp; t < CHUNK; t += NWARPS) {
            const int gt = cstart + t;
            if (gt >= len) break;
            const int blk = bt[seq * BPS + (gt >> 4)];
            const float4 v4 = *(const float4*)(vc +
                (((size_t)blk * KVH + kvh) * BS + (gt & 15)) * HD + d4 * 4);
            #pragma unroll
            for (int g = 0; g < GROUPS; ++g) {
                const float p = s_sc[g][t];
                acc[g][0] += p * v4.x;
                acc[g][1] += p * v4.y;
                acc[g][2] += p * v4.z;
                acc[g][3] += p * v4.w;
            }
        }

        #pragma unroll
        for (int g = 0; g < GROUPS; ++g) {
            float4* r = (float4*)&s_red[warp][g * HD + d4 * 4];
            *r = make_float4(acc[g][0], acc[g][1], acc[g][2], acc[g][3]);
        }
    }
    __syncthreads();

    // Cross-warp reduce + write unnormalized partial output
    for (int idx = tid; idx < GROUPS * HD; idx += NTHREADS) {
        float s = 0.0f;
        #pragma unroll
        for (int w = 0; w < NWARPS; ++w) s += s_red[w][idx];
        g_pout[(size_t)pbase * HD + idx] = s;
    }
}

// Combine split-KV partials with global log-sum-exp and normalize.
__global__ __launch_bounds__(GROUPS * HD)
void attn_reduce_kernel(float* __restrict__ out)
{
    const int sk  = blockIdx.x;            // seq*KVH + kvh
    const int seq = sk / KVH;
    const int kvh = sk % KVH;
    const int g   = threadIdx.x / HD;
    const int d   = threadIdx.x % HD;

    float M = -FLT_MAX;
    #pragma unroll
    for (int c = 0; c < NCHUNK; ++c)
        M = fmaxf(M, g_pm[(sk * NCHUNK + c) * GROUPS + g]);

    float L = 0.0f, o = 0.0f;
    #pragma unroll
    for (int c = 0; c < NCHUNK; ++c) {
        const int   pidx = (sk * NCHUNK + c) * GROUPS + g;
        const float l    = g_pl[pidx];
        if (l > 0.0f) {
            const float f = __expf(g_pm[pidx] - M);
            L += l * f;
            o += g_pout[(size_t)pidx * HD + d] * f;
        }
    }
    out[(size_t)seq * (NH * HD) + (kvh * GROUPS + g) * HD + d] = o / L;
}

extern "C" void kernel_launch(void* const* d_in, const int* in_sizes, int n_in,
                              void* d_out, int out_size)
{
    const float* q    = (const float*)d_in[0];
    const float* kc   = (const float*)d_in[1];
    const float* vc   = (const float*)d_in[2];
    const int*   bt   = (const int*)d_in[3];
    const int*   lens = (const int*)d_in[4];
    float* out = (float*)d_out;

    attn_chunk_kernel<<<BSZ * KVH * NCHUNK, NTHREADS>>>(q, kc, vc, bt, lens);
    attn_reduce_kernel<<<BSZ * KVH, GROUPS * HD>>>(out);
}